// round 7
// baseline (speedup 1.0000x reference)
#include <cuda_runtime.h>
#include <math.h>

// ---- problem constants ----
#define HID    2048
#define NH     32
#define KVH    8
#define HD     64
#define BATCH  2
#define SEQ    2048
#define MROWS  (BATCH * SEQ)   // 4096
#define KVDIM  (KVH * HD)      // 512

typedef unsigned long long u64;

// ---- packed f32x2 helpers (Blackwell-only PTX; 2 FMAs per issue) ----
__device__ __forceinline__ u64 dup2(float x) {
    u64 r;
    unsigned xi = __float_as_uint(x);
    asm("mov.b64 %0, {%1, %1};" : "=l"(r) : "r"(xi));
    return r;
}
__device__ __forceinline__ void fma2(u64& d, u64 a, u64 b) {
    asm("fma.rn.f32x2 %0, %1, %2, %0;" : "+l"(d) : "l"(a), "l"(b));
}
__device__ __forceinline__ void mul2(u64& d, u64 a) {
    asm("mul.rn.f32x2 %0, %0, %1;" : "+l"(d) : "l"(a));
}
__device__ __forceinline__ float2 unpack2(u64 v) {
    unsigned lo, hi;
    asm("mov.b64 {%0, %1}, %2;" : "=r"(lo), "=r"(hi) : "l"(v));
    return make_float2(__uint_as_float(lo), __uint_as_float(hi));
}

// ---- scratch (device globals: allocation-free) ----
__device__ float g_q[(size_t)MROWS * HID];
__device__ float g_k[(size_t)MROWS * KVDIM];
__device__ float g_v[(size_t)MROWS * KVDIM];
__device__ float g_att[(size_t)MROWS * HID];

// ============================================================
// SGEMM: C[M,N] = A[M,K] @ B[K,N], row-major fp32.
// BM=BN=128, BK=16, 256 threads, 8x8 microtile, f32x2 packed FMA.
// ============================================================
__global__ void __launch_bounds__(256)
sgemm_kernel(const float* __restrict__ A, const float* __restrict__ Bm,
             float* __restrict__ C, int M, int N, int K)
{
    __shared__ float As[16][128 + 4];   // transposed A tile, padded
    __shared__ float Bs[16][128];

    const int tid = threadIdx.x;
    const int tx = tid & 15;
    const int ty = tid >> 4;
    const int rowBase = blockIdx.y * 128;
    const int colBase = blockIdx.x * 128;

    // packed accumulators: acc[i][jp] holds columns (2*jp, 2*jp+1)
    u64 acc[8][4];
#pragma unroll
    for (int i = 0; i < 8; ++i)
#pragma unroll
        for (int j = 0; j < 4; ++j) acc[i][j] = 0ULL;  // bits of (0.f, 0.f)

    for (int kt = 0; kt < K; kt += 16) {
        // load A tile (128x16) -> As[k][m]
#pragma unroll
        for (int p = 0; p < 2; ++p) {
            int id = tid + p * 256;
            int arow = id >> 2;       // 0..127
            int ac4 = id & 3;         // 0..3
            float4 v = *(const float4*)&A[(size_t)(rowBase + arow) * K + kt + ac4 * 4];
            As[ac4 * 4 + 0][arow] = v.x;
            As[ac4 * 4 + 1][arow] = v.y;
            As[ac4 * 4 + 2][arow] = v.z;
            As[ac4 * 4 + 3][arow] = v.w;
        }
        // load B tile (16x128) -> Bs[k][n]
#pragma unroll
        for (int p = 0; p < 2; ++p) {
            int id = tid + p * 256;
            int brow = id >> 5;       // 0..15
            int bc4 = id & 31;        // 0..31
            *(float4*)&Bs[brow][bc4 * 4] =
                *(const float4*)&Bm[(size_t)(kt + brow) * N + colBase + bc4 * 4];
        }
        __syncthreads();

#pragma unroll
        for (int k = 0; k < 16; ++k) {
            float a[8];
            *(float4*)&a[0] = *(const float4*)&As[k][ty * 8];
            *(float4*)&a[4] = *(const float4*)&As[k][ty * 8 + 4];
            u64 ap[8];
#pragma unroll
            for (int i = 0; i < 8; ++i) ap[i] = dup2(a[i]);

            const u64* bpr = (const u64*)&Bs[k][tx * 8];   // 4x LDS.64, pairs
            u64 bp0 = bpr[0], bp1 = bpr[1], bp2 = bpr[2], bp3 = bpr[3];
#pragma unroll
            for (int i = 0; i < 8; ++i) {
                fma2(acc[i][0], ap[i], bp0);
                fma2(acc[i][1], ap[i], bp1);
                fma2(acc[i][2], ap[i], bp2);
                fma2(acc[i][3], ap[i], bp3);
            }
        }
        __syncthreads();
    }

#pragma unroll
    for (int i = 0; i < 8; ++i) {
        size_t r = (size_t)(rowBase + ty * 8 + i);
        float2 c0 = unpack2(acc[i][0]);
        float2 c1 = unpack2(acc[i][1]);
        float2 c2 = unpack2(acc[i][2]);
        float2 c3 = unpack2(acc[i][3]);
        *(float4*)&C[r * N + colBase + tx * 8]     = make_float4(c0.x, c0.y, c1.x, c1.y);
        *(float4*)&C[r * N + colBase + tx * 8 + 4] = make_float4(c2.x, c2.y, c3.x, c3.y);
    }
}

// ============================================================
// RoPE applied in place to q [MROWS, NH*HD] and k [MROWS, KVH*HD].
// ============================================================
__global__ void rope_kernel(float* __restrict__ q, float* __restrict__ k)
{
    const int QP = MROWS * NH * (HD / 2);
    const int KP = MROWS * KVH * (HD / 2);
    int idx = blockIdx.x * blockDim.x + threadIdx.x;
    if (idx >= QP + KP) return;

    float* buf;
    int row, head, j, rowdim;
    if (idx < QP) {
        int t = idx;
        j = t & 31; t >>= 5;
        head = t & (NH - 1); t >>= 5;   // NH = 32
        row = t;
        buf = q; rowdim = NH * HD;
    } else {
        int t = idx - QP;
        j = t & 31; t >>= 5;
        head = t & (KVH - 1); t >>= 3;  // KVH = 8
        row = t;
        buf = k; rowdim = KVH * HD;
    }
    int pos = row & (SEQ - 1);
    float inv_freq = exp2f(-(float)j * 0.41524101186092029f);
    float ang = (float)pos * inv_freq;
    float c, s;
    sincosf(ang, &s, &c);

    float* p = buf + (size_t)row * rowdim + head * HD + j;
    float x1 = p[0], x2 = p[32];
    p[0]  = x1 * c - x2 * s;
    p[32] = x2 * c + x1 * s;
}

// ============================================================
// Flash attention, non-causal, GQA. f32x2 packed FMA mainloops.
// Grid: (SEQ/64, NH, BATCH). 256 threads = 16x16, 4x4 microtiles.
// ============================================================
__global__ void __launch_bounds__(256)
attn_kernel(const float* __restrict__ q, const float* __restrict__ k,
            const float* __restrict__ v, float* __restrict__ o)
{
    extern __shared__ float sm[];
    float* Qs  = sm;                // [64][64] row-major (m, d)
    float* Kts = sm + 64 * 64;      // [64][64] d-major (d, n), swizzled
    float* Vs  = sm + 2 * 64 * 64;  // [64][64] row-major (n, d)
    float* Ps  = sm + 3 * 64 * 64;  // [64][64] row-major (m, n)

    const int tid = threadIdx.x;
    const int tx = tid & 15;
    const int ty = tid >> 4;
    const int qb = blockIdx.x * 64;
    const int h  = blockIdx.y;
    const int b  = blockIdx.z;
    const int kvh = h >> 2;

    const float* qg = q + (size_t)b * SEQ * HID + (size_t)h * HD;
    const float* kg = k + (size_t)b * SEQ * KVDIM + (size_t)kvh * HD;
    const float* vg = v + (size_t)b * SEQ * KVDIM + (size_t)kvh * HD;
    float* og = o + (size_t)b * SEQ * HID + (size_t)h * HD;

    // load Q tile, folding in 1/sqrt(64) = 0.125 scale
#pragma unroll
    for (int p = 0; p < 4; ++p) {
        int id = tid + p * 256;
        int m = id >> 4, d4 = id & 15;
        float4 vq = *(const float4*)&qg[(size_t)(qb + m) * HID + d4 * 4];
        vq.x *= 0.125f; vq.y *= 0.125f; vq.z *= 0.125f; vq.w *= 0.125f;
        *(float4*)&Qs[m * 64 + d4 * 4] = vq;
    }

    u64 accp[4][2];           // packed O accumulators: [row][pair of d-cols]
    float mi[4], li[4];
#pragma unroll
    for (int r = 0; r < 4; ++r) {
        mi[r] = -3.0e38f;
        li[r] = 0.0f;
        accp[r][0] = 0ULL;
        accp[r][1] = 0ULL;
    }

    for (int kb = 0; kb < SEQ; kb += 64) {
        __syncthreads();  // guards Qs(load) + Kts/Vs/Ps reuse across iterations

        // load K (transposed+swizzled) and V tiles
#pragma unroll
        for (int p = 0; p < 4; ++p) {
            int id = tid + p * 256;
            int n = id >> 4, d4 = id & 15;
            float4 kv = *(const float4*)&kg[(size_t)(kb + n) * KVDIM + d4 * 4];
            float vals[4] = {kv.x, kv.y, kv.z, kv.w};
#pragma unroll
            for (int i = 0; i < 4; ++i) {
                int d = d4 * 4 + i;
                Kts[d * 64 + ((((n >> 2) ^ (d & 15)) << 2) | (n & 3))] = vals[i];
            }
            float4 vv = *(const float4*)&vg[(size_t)(kb + n) * KVDIM + d4 * 4];
            *(float4*)&Vs[n * 64 + d4 * 4] = vv;
        }
        __syncthreads();

        // scores S = Q K^T (already scaled), packed pairs along n
        u64 scp[4][2];
#pragma unroll
        for (int r = 0; r < 4; ++r) { scp[r][0] = 0ULL; scp[r][1] = 0ULL; }

#pragma unroll 16
        for (int d = 0; d < 64; ++d) {
            const u64* kp = (const u64*)&Kts[d * 64 + ((tx ^ (d & 15)) << 2)];
            u64 k0 = kp[0], k1 = kp[1];
            u64 q0 = dup2(Qs[(4 * ty + 0) * 64 + d]);
            u64 q1 = dup2(Qs[(4 * ty + 1) * 64 + d]);
            u64 q2 = dup2(Qs[(4 * ty + 2) * 64 + d]);
            u64 q3 = dup2(Qs[(4 * ty + 3) * 64 + d]);
            fma2(scp[0][0], q0, k0); fma2(scp[0][1], q0, k1);
            fma2(scp[1][0], q1, k0); fma2(scp[1][1], q1, k1);
            fma2(scp[2][0], q2, k0); fma2(scp[2][1], q2, k1);
            fma2(scp[3][0], q3, k0); fma2(scp[3][1], q3, k1);
        }

        // online softmax update (row reduction across the 16 tx lanes)
#pragma unroll
        for (int r = 0; r < 4; ++r) {
            float2 s01 = unpack2(scp[r][0]);
            float2 s23 = unpack2(scp[r][1]);
            float sc0 = s01.x, sc1 = s01.y, sc2 = s23.x, sc3 = s23.y;

            float m = fmaxf(fmaxf(sc0, sc1), fmaxf(sc2, sc3));
            m = fmaxf(m, __shfl_xor_sync(0xffffffffu, m, 1));
            m = fmaxf(m, __shfl_xor_sync(0xffffffffu, m, 2));
            m = fmaxf(m, __shfl_xor_sync(0xffffffffu, m, 4));
            m = fmaxf(m, __shfl_xor_sync(0xffffffffu, m, 8));
            float mnew = fmaxf(mi[r], m);
            float alpha = __expf(mi[r] - mnew);
            mi[r] = mnew;

            sc0 = __expf(sc0 - mnew);
            sc1 = __expf(sc1 - mnew);
            sc2 = __expf(sc2 - mnew);
            sc3 = __expf(sc3 - mnew);
            float rs = sc0 + sc1 + sc2 + sc3;
            rs += __shfl_xor_sync(0xffffffffu, rs, 1);
            rs += __shfl_xor_sync(0xffffffffu, rs, 2);
            rs += __shfl_xor_sync(0xffffffffu, rs, 4);
            rs += __shfl_xor_sync(0xffffffffu, rs, 8);
            li[r] = li[r] * alpha + rs;

            u64 ad = dup2(alpha);
            mul2(accp[r][0], ad);
            mul2(accp[r][1], ad);

            *(float4*)&Ps[(4 * ty + r) * 64 + 4 * tx] = make_float4(sc0, sc1, sc2, sc3);
        }
        __syncthreads();

        // O += P @ V, packed pairs along d
#pragma unroll 16
        for (int kk = 0; kk < 64; ++kk) {
            const u64* vp = (const u64*)&Vs[kk * 64 + 4 * tx];
            u64 v0 = vp[0], v1 = vp[1];
            u64 p0 = dup2(Ps[(4 * ty + 0) * 64 + kk]);
            u64 p1 = dup2(Ps[(4 * ty + 1) * 64 + kk]);
            u64 p2 = dup2(Ps[(4 * ty + 2) * 64 + kk]);
            u64 p3 = dup2(Ps[(4 * ty + 3) * 64 + kk]);
            fma2(accp[0][0], p0, v0); fma2(accp[0][1], p0, v1);
            fma2(accp[1][0], p1, v0); fma2(accp[1][1], p1, v1);
            fma2(accp[2][0], p2, v0); fma2(accp[2][1], p2, v1);
            fma2(accp[3][0], p3, v0); fma2(accp[3][1], p3, v1);
        }
    }

    // epilogue: normalize and store [b, s, h, d]
#pragma unroll
    for (int r = 0; r < 4; ++r) {
        float inv = 1.0f / li[r];
        float2 a01 = unpack2(accp[r][0]);
        float2 a23 = unpack2(accp[r][1]);
        float4 ov = make_float4(a01.x * inv, a01.y * inv, a23.x * inv, a23.y * inv);
        *(float4*)&og[(size_t)(qb + 4 * ty + r) * HID + 4 * tx] = ov;
    }
}

// ============================================================
// launch
// ============================================================
extern "C" void kernel_launch(void* const* d_in, const int* in_sizes, int n_in,
                              void* d_out, int out_size)
{
    const float* x  = (const float*)d_in[0];
    const float* wq = (const float*)d_in[1];
    const float* wk = (const float*)d_in[2];
    const float* wv = (const float*)d_in[3];
    const float* wo = (const float*)d_in[4];
    float* out = (float*)d_out;

    float *qp, *kp, *vp, *ap;
    cudaGetSymbolAddress((void**)&qp, g_q);
    cudaGetSymbolAddress((void**)&kp, g_k);
    cudaGetSymbolAddress((void**)&vp, g_v);
    cudaGetSymbolAddress((void**)&ap, g_att);

    dim3 blk(256);

    // QKV projections
    sgemm_kernel<<<dim3(HID / 128, MROWS / 128), blk>>>(x, wq, qp, MROWS, HID, HID);
    sgemm_kernel<<<dim3(KVDIM / 128, MROWS / 128), blk>>>(x, wk, kp, MROWS, KVDIM, HID);
    sgemm_kernel<<<dim3(KVDIM / 128, MROWS / 128), blk>>>(x, wv, vp, MROWS, KVDIM, HID);

    // RoPE (q and k in place)
    int total = MROWS * NH * (HD / 2) + MROWS * KVH * (HD / 2);
    rope_kernel<<<(total + 255) / 256, 256>>>(qp, kp);

    // attention
    cudaFuncSetAttribute(attn_kernel, cudaFuncAttributeMaxDynamicSharedMemorySize, 65536);
    attn_kernel<<<dim3(SEQ / 64, NH, BATCH), blk, 65536>>>(qp, kp, vp, ap);

    // output projection -> d_out
    sgemm_kernel<<<dim3(HID / 128, MROWS / 128), blk>>>(ap, wo, out, MROWS, HID, HID);
}

// round 8
// speedup vs baseline: 1.0004x; 1.0004x over previous
#include <cuda_runtime.h>
#include <math.h>

// ---- problem constants ----
#define HID    2048
#define NH     32
#define KVH    8
#define HD     64
#define BATCH  2
#define SEQ    2048
#define MROWS  (BATCH * SEQ)   // 4096
#define KVDIM  (KVH * HD)      // 512

typedef unsigned long long u64;

// ---- packed f32x2 helpers (Blackwell-only PTX; 2 FMAs per issue) ----
__device__ __forceinline__ u64 dup2(float x) {
    u64 r;
    unsigned xi = __float_as_uint(x);
    asm("mov.b64 %0, {%1, %1};" : "=l"(r) : "r"(xi));
    return r;
}
__device__ __forceinline__ void fma2(u64& d, u64 a, u64 b) {
    asm("fma.rn.f32x2 %0, %1, %2, %0;" : "+l"(d) : "l"(a), "l"(b));
}
__device__ __forceinline__ void mul2(u64& d, u64 a) {
    asm("mul.rn.f32x2 %0, %0, %1;" : "+l"(d) : "l"(a));
}
__device__ __forceinline__ float2 unpack2(u64 v) {
    unsigned lo, hi;
    asm("mov.b64 {%0, %1}, %2;" : "=r"(lo), "=r"(hi) : "l"(v));
    return make_float2(__uint_as_float(lo), __uint_as_float(hi));
}

// ---- scratch (device globals: allocation-free) ----
__device__ float g_q[(size_t)MROWS * HID];
__device__ float g_k[(size_t)MROWS * KVDIM];
__device__ float g_v[(size_t)MROWS * KVDIM];
__device__ float g_att[(size_t)MROWS * HID];

// ============================================================
// SGEMM: C[M,N] = A[M,K] @ B[K,N], row-major fp32.
// BM=BN=128, BK=16, 256 threads, 8x8 microtile, f32x2 packed FMA.
// ============================================================
__global__ void __launch_bounds__(256)
sgemm_kernel(const float* __restrict__ A, const float* __restrict__ Bm,
             float* __restrict__ C, int M, int N, int K)
{
    __shared__ float As[16][128 + 4];   // transposed A tile, padded
    __shared__ float Bs[16][128];

    const int tid = threadIdx.x;
    const int tx = tid & 15;
    const int ty = tid >> 4;
    const int rowBase = blockIdx.y * 128;
    const int colBase = blockIdx.x * 128;

    // packed accumulators: acc[i][jp] holds columns (2*jp, 2*jp+1)
    u64 acc[8][4];
#pragma unroll
    for (int i = 0; i < 8; ++i)
#pragma unroll
        for (int j = 0; j < 4; ++j) acc[i][j] = 0ULL;  // bits of (0.f, 0.f)

    for (int kt = 0; kt < K; kt += 16) {
        // load A tile (128x16) -> As[k][m]
#pragma unroll
        for (int p = 0; p < 2; ++p) {
            int id = tid + p * 256;
            int arow = id >> 2;       // 0..127
            int ac4 = id & 3;         // 0..3
            float4 v = *(const float4*)&A[(size_t)(rowBase + arow) * K + kt + ac4 * 4];
            As[ac4 * 4 + 0][arow] = v.x;
            As[ac4 * 4 + 1][arow] = v.y;
            As[ac4 * 4 + 2][arow] = v.z;
            As[ac4 * 4 + 3][arow] = v.w;
        }
        // load B tile (16x128) -> Bs[k][n]
#pragma unroll
        for (int p = 0; p < 2; ++p) {
            int id = tid + p * 256;
            int brow = id >> 5;       // 0..15
            int bc4 = id & 31;        // 0..31
            *(float4*)&Bs[brow][bc4 * 4] =
                *(const float4*)&Bm[(size_t)(kt + brow) * N + colBase + bc4 * 4];
        }
        __syncthreads();

#pragma unroll
        for (int k = 0; k < 16; ++k) {
            float a[8];
            *(float4*)&a[0] = *(const float4*)&As[k][ty * 8];
            *(float4*)&a[4] = *(const float4*)&As[k][ty * 8 + 4];
            u64 ap[8];
#pragma unroll
            for (int i = 0; i < 8; ++i) ap[i] = dup2(a[i]);

            const u64* bpr = (const u64*)&Bs[k][tx * 8];   // 4x LDS.64, pairs
            u64 bp0 = bpr[0], bp1 = bpr[1], bp2 = bpr[2], bp3 = bpr[3];
#pragma unroll
            for (int i = 0; i < 8; ++i) {
                fma2(acc[i][0], ap[i], bp0);
                fma2(acc[i][1], ap[i], bp1);
                fma2(acc[i][2], ap[i], bp2);
                fma2(acc[i][3], ap[i], bp3);
            }
        }
        __syncthreads();
    }

#pragma unroll
    for (int i = 0; i < 8; ++i) {
        size_t r = (size_t)(rowBase + ty * 8 + i);
        float2 c0 = unpack2(acc[i][0]);
        float2 c1 = unpack2(acc[i][1]);
        float2 c2 = unpack2(acc[i][2]);
        float2 c3 = unpack2(acc[i][3]);
        *(float4*)&C[r * N + colBase + tx * 8]     = make_float4(c0.x, c0.y, c1.x, c1.y);
        *(float4*)&C[r * N + colBase + tx * 8 + 4] = make_float4(c2.x, c2.y, c3.x, c3.y);
    }
}

// ============================================================
// RoPE applied in place to q [MROWS, NH*HD] and k [MROWS, KVH*HD].
// ============================================================
__global__ void rope_kernel(float* __restrict__ q, float* __restrict__ k)
{
    const int QP = MROWS * NH * (HD / 2);
    const int KP = MROWS * KVH * (HD / 2);
    int idx = blockIdx.x * blockDim.x + threadIdx.x;
    if (idx >= QP + KP) return;

    float* buf;
    int row, head, j, rowdim;
    if (idx < QP) {
        int t = idx;
        j = t & 31; t >>= 5;
        head = t & (NH - 1); t >>= 5;   // NH = 32
        row = t;
        buf = q; rowdim = NH * HD;
    } else {
        int t = idx - QP;
        j = t & 31; t >>= 5;
        head = t & (KVH - 1); t >>= 3;  // KVH = 8
        row = t;
        buf = k; rowdim = KVH * HD;
    }
    int pos = row & (SEQ - 1);
    float inv_freq = exp2f(-(float)j * 0.41524101186092029f);
    float ang = (float)pos * inv_freq;
    float c, s;
    sincosf(ang, &s, &c);

    float* p = buf + (size_t)row * rowdim + head * HD + j;
    float x1 = p[0], x2 = p[32];
    p[0]  = x1 * c - x2 * s;
    p[32] = x2 * c + x1 * s;
}

// ============================================================
// Flash attention, non-causal, GQA. f32x2 packed FMA mainloops.
// Grid: (SEQ/64, NH, BATCH). 256 threads = 16x16, 4x4 microtiles.
// ============================================================
__global__ void __launch_bounds__(256)
attn_kernel(const float* __restrict__ q, const float* __restrict__ k,
            const float* __restrict__ v, float* __restrict__ o)
{
    extern __shared__ float sm[];
    float* Qs  = sm;                // [64][64] row-major (m, d)
    float* Kts = sm + 64 * 64;      // [64][64] d-major (d, n), swizzled
    float* Vs  = sm + 2 * 64 * 64;  // [64][64] row-major (n, d)
    float* Ps  = sm + 3 * 64 * 64;  // [64][64] row-major (m, n)

    const int tid = threadIdx.x;
    const int tx = tid & 15;
    const int ty = tid >> 4;
    const int qb = blockIdx.x * 64;
    const int h  = blockIdx.y;
    const int b  = blockIdx.z;
    const int kvh = h >> 2;

    const float* qg = q + (size_t)b * SEQ * HID + (size_t)h * HD;
    const float* kg = k + (size_t)b * SEQ * KVDIM + (size_t)kvh * HD;
    const float* vg = v + (size_t)b * SEQ * KVDIM + (size_t)kvh * HD;
    float* og = o + (size_t)b * SEQ * HID + (size_t)h * HD;

    // load Q tile, folding in 1/sqrt(64) = 0.125 scale
#pragma unroll
    for (int p = 0; p < 4; ++p) {
        int id = tid + p * 256;
        int m = id >> 4, d4 = id & 15;
        float4 vq = *(const float4*)&qg[(size_t)(qb + m) * HID + d4 * 4];
        vq.x *= 0.125f; vq.y *= 0.125f; vq.z *= 0.125f; vq.w *= 0.125f;
        *(float4*)&Qs[m * 64 + d4 * 4] = vq;
    }

    u64 accp[4][2];           // packed O accumulators: [row][pair of d-cols]
    float mi[4], li[4];
#pragma unroll
    for (int r = 0; r < 4; ++r) {
        mi[r] = -3.0e38f;
        li[r] = 0.0f;
        accp[r][0] = 0ULL;
        accp[r][1] = 0ULL;
    }

    for (int kb = 0; kb < SEQ; kb += 64) {
        __syncthreads();  // guards Qs(load) + Kts/Vs/Ps reuse across iterations

        // load K (transposed+swizzled) and V tiles
#pragma unroll
        for (int p = 0; p < 4; ++p) {
            int id = tid + p * 256;
            int n = id >> 4, d4 = id & 15;
            float4 kv = *(const float4*)&kg[(size_t)(kb + n) * KVDIM + d4 * 4];
            float vals[4] = {kv.x, kv.y, kv.z, kv.w};
#pragma unroll
            for (int i = 0; i < 4; ++i) {
                int d = d4 * 4 + i;
                Kts[d * 64 + ((((n >> 2) ^ (d & 15)) << 2) | (n & 3))] = vals[i];
            }
            float4 vv = *(const float4*)&vg[(size_t)(kb + n) * KVDIM + d4 * 4];
            *(float4*)&Vs[n * 64 + d4 * 4] = vv;
        }
        __syncthreads();

        // scores S = Q K^T (already scaled), packed pairs along n
        u64 scp[4][2];
#pragma unroll
        for (int r = 0; r < 4; ++r) { scp[r][0] = 0ULL; scp[r][1] = 0ULL; }

#pragma unroll 16
        for (int d = 0; d < 64; ++d) {
            const u64* kp = (const u64*)&Kts[d * 64 + ((tx ^ (d & 15)) << 2)];
            u64 k0 = kp[0], k1 = kp[1];
            u64 q0 = dup2(Qs[(4 * ty + 0) * 64 + d]);
            u64 q1 = dup2(Qs[(4 * ty + 1) * 64 + d]);
            u64 q2 = dup2(Qs[(4 * ty + 2) * 64 + d]);
            u64 q3 = dup2(Qs[(4 * ty + 3) * 64 + d]);
            fma2(scp[0][0], q0, k0); fma2(scp[0][1], q0, k1);
            fma2(scp[1][0], q1, k0); fma2(scp[1][1], q1, k1);
            fma2(scp[2][0], q2, k0); fma2(scp[2][1], q2, k1);
            fma2(scp[3][0], q3, k0); fma2(scp[3][1], q3, k1);
        }

        // online softmax update (row reduction across the 16 tx lanes)
#pragma unroll
        for (int r = 0; r < 4; ++r) {
            float2 s01 = unpack2(scp[r][0]);
            float2 s23 = unpack2(scp[r][1]);
            float sc0 = s01.x, sc1 = s01.y, sc2 = s23.x, sc3 = s23.y;

            float m = fmaxf(fmaxf(sc0, sc1), fmaxf(sc2, sc3));
            m = fmaxf(m, __shfl_xor_sync(0xffffffffu, m, 1));
            m = fmaxf(m, __shfl_xor_sync(0xffffffffu, m, 2));
            m = fmaxf(m, __shfl_xor_sync(0xffffffffu, m, 4));
            m = fmaxf(m, __shfl_xor_sync(0xffffffffu, m, 8));
            float mnew = fmaxf(mi[r], m);
            float alpha = __expf(mi[r] - mnew);
            mi[r] = mnew;

            sc0 = __expf(sc0 - mnew);
            sc1 = __expf(sc1 - mnew);
            sc2 = __expf(sc2 - mnew);
            sc3 = __expf(sc3 - mnew);
            float rs = sc0 + sc1 + sc2 + sc3;
            rs += __shfl_xor_sync(0xffffffffu, rs, 1);
            rs += __shfl_xor_sync(0xffffffffu, rs, 2);
            rs += __shfl_xor_sync(0xffffffffu, rs, 4);
            rs += __shfl_xor_sync(0xffffffffu, rs, 8);
            li[r] = li[r] * alpha + rs;

            u64 ad = dup2(alpha);
            mul2(accp[r][0], ad);
            mul2(accp[r][1], ad);

            *(float4*)&Ps[(4 * ty + r) * 64 + 4 * tx] = make_float4(sc0, sc1, sc2, sc3);
        }
        __syncthreads();

        // O += P @ V, packed pairs along d
#pragma unroll 16
        for (int kk = 0; kk < 64; ++kk) {
            const u64* vp = (const u64*)&Vs[kk * 64 + 4 * tx];
            u64 v0 = vp[0], v1 = vp[1];
            u64 p0 = dup2(Ps[(4 * ty + 0) * 64 + kk]);
            u64 p1 = dup2(Ps[(4 * ty + 1) * 64 + kk]);
            u64 p2 = dup2(Ps[(4 * ty + 2) * 64 + kk]);
            u64 p3 = dup2(Ps[(4 * ty + 3) * 64 + kk]);
            fma2(accp[0][0], p0, v0); fma2(accp[0][1], p0, v1);
            fma2(accp[1][0], p1, v0); fma2(accp[1][1], p1, v1);
            fma2(accp[2][0], p2, v0); fma2(accp[2][1], p2, v1);
            fma2(accp[3][0], p3, v0); fma2(accp[3][1], p3, v1);
        }
    }

    // epilogue: normalize and store [b, s, h, d]
#pragma unroll
    for (int r = 0; r < 4; ++r) {
        float inv = 1.0f / li[r];
        float2 a01 = unpack2(accp[r][0]);
        float2 a23 = unpack2(accp[r][1]);
        float4 ov = make_float4(a01.x * inv, a01.y * inv, a23.x * inv, a23.y * inv);
        *(float4*)&og[(size_t)(qb + 4 * ty + r) * HID + 4 * tx] = ov;
    }
}

// ============================================================
// launch
// ============================================================
extern "C" void kernel_launch(void* const* d_in, const int* in_sizes, int n_in,
                              void* d_out, int out_size)
{
    const float* x  = (const float*)d_in[0];
    const float* wq = (const float*)d_in[1];
    const float* wk = (const float*)d_in[2];
    const float* wv = (const float*)d_in[3];
    const float* wo = (const float*)d_in[4];
    float* out = (float*)d_out;

    float *qp, *kp, *vp, *ap;
    cudaGetSymbolAddress((void**)&qp, g_q);
    cudaGetSymbolAddress((void**)&kp, g_k);
    cudaGetSymbolAddress((void**)&vp, g_v);
    cudaGetSymbolAddress((void**)&ap, g_att);

    dim3 blk(256);

    // QKV projections
    sgemm_kernel<<<dim3(HID / 128, MROWS / 128), blk>>>(x, wq, qp, MROWS, HID, HID);
    sgemm_kernel<<<dim3(KVDIM / 128, MROWS / 128), blk>>>(x, wk, kp, MROWS, KVDIM, HID);
    sgemm_kernel<<<dim3(KVDIM / 128, MROWS / 128), blk>>>(x, wv, vp, MROWS, KVDIM, HID);

    // RoPE (q and k in place)
    int total = MROWS * NH * (HD / 2) + MROWS * KVH * (HD / 2);
    rope_kernel<<<(total + 255) / 256, 256>>>(qp, kp);

    // attention
    cudaFuncSetAttribute(attn_kernel, cudaFuncAttributeMaxDynamicSharedMemorySize, 65536);
    attn_kernel<<<dim3(SEQ / 64, NH, BATCH), blk, 65536>>>(qp, kp, vp, ap);

    // output projection -> d_out
    sgemm_kernel<<<dim3(HID / 128, MROWS / 128), blk>>>(ap, wo, out, MROWS, HID, HID);
}

// round 9
// speedup vs baseline: 1.1937x; 1.1932x over previous
#include <cuda_runtime.h>
#include <math.h>

// ---- problem constants ----
#define HID    2048
#define NH     32
#define KVH    8
#define HD     64
#define BATCH  2
#define SEQ    2048
#define MROWS  (BATCH * SEQ)   // 4096
#define KVDIM  (KVH * HD)      // 512

// ---- scratch (device globals: allocation-free) ----
__device__ float g_q[(size_t)MROWS * HID];
__device__ float g_k[(size_t)MROWS * KVDIM];
__device__ float g_v[(size_t)MROWS * KVDIM];
__device__ float g_att[(size_t)MROWS * HID];

// ---- tf32 helpers ----
__device__ __forceinline__ unsigned to_tf32(float x) {
    unsigned r;
    asm("cvt.rna.tf32.f32 %0, %1;" : "=r"(r) : "f"(x));
    return r;
}
__device__ __forceinline__ void split_tf32(float x, unsigned& hi, unsigned& lo) {
    hi = to_tf32(x);
    lo = to_tf32(x - __uint_as_float(hi));
}
// D += A(16x8 row) @ B(8x8 col), tf32 in / f32 accum
__device__ __forceinline__ void mma_tf32(float* c, const unsigned* a, const unsigned* b) {
    asm volatile(
        "mma.sync.aligned.m16n8k8.row.col.f32.tf32.tf32.f32 "
        "{%0,%1,%2,%3}, {%4,%5,%6,%7}, {%8,%9}, {%0,%1,%2,%3};"
        : "+f"(c[0]), "+f"(c[1]), "+f"(c[2]), "+f"(c[3])
        : "r"(a[0]), "r"(a[1]), "r"(a[2]), "r"(a[3]), "r"(b[0]), "r"(b[1]));
}

// ============================================================
// GEMM: C[M,N] = A[M,K] @ B[K,N], row-major fp32, tf32x2 MMA.
// 128x128 tile, BK=16, 256 thr = 8 warps (4M x 2N).
// Warp tile 32x64: 2 m-tiles x 8 n-tiles of m16n8k8.
// ============================================================
__global__ void __launch_bounds__(256)
gemm_tf32_kernel(const float* __restrict__ A, const float* __restrict__ Bm,
                 float* __restrict__ C, int M, int N, int K)
{
    __shared__ float Ash[16][132];   // [k][m] hi
    __shared__ float Asl[16][132];   // [k][m] lo
    __shared__ float Bsh[16][132];   // [k][n] hi
    __shared__ float Bsl[16][132];   // [k][n] lo

    const int tid  = threadIdx.x;
    const int lane = tid & 31;
    const int wid  = tid >> 5;
    const int g    = lane >> 2;   // groupID 0..7
    const int q4   = lane & 3;    // quad lane 0..3
    const int warpM = wid >> 1;   // 0..3
    const int warpN = wid & 1;    // 0..1
    const int rowBase = blockIdx.y * 128;
    const int colBase = blockIdx.x * 128;

    float acc[2][8][4] = {};

    for (int kt = 0; kt < K; kt += 16) {
        __syncthreads();
        // A tile 128x16 -> transposed hi/lo
#pragma unroll
        for (int p = 0; p < 2; ++p) {
            int id = tid + p * 256;
            int ar = id >> 2;
            int ac = (id & 3) * 4;
            float4 v = *(const float4*)&A[(size_t)(rowBase + ar) * K + kt + ac];
            float vv[4] = {v.x, v.y, v.z, v.w};
#pragma unroll
            for (int j = 0; j < 4; ++j) {
                unsigned h, l;
                split_tf32(vv[j], h, l);
                Ash[ac + j][ar] = __uint_as_float(h);
                Asl[ac + j][ar] = __uint_as_float(l);
            }
        }
        // B tile 16x128 -> hi/lo
#pragma unroll
        for (int p = 0; p < 2; ++p) {
            int id = tid + p * 256;
            int br = id >> 5;
            int bc = (id & 31) * 4;
            float4 v = *(const float4*)&Bm[(size_t)(kt + br) * N + colBase + bc];
            float vv[4] = {v.x, v.y, v.z, v.w};
            float hv[4], lv[4];
#pragma unroll
            for (int j = 0; j < 4; ++j) {
                unsigned h, l;
                split_tf32(vv[j], h, l);
                hv[j] = __uint_as_float(h);
                lv[j] = __uint_as_float(l);
            }
            *(float4*)&Bsh[br][bc] = make_float4(hv[0], hv[1], hv[2], hv[3]);
            *(float4*)&Bsl[br][bc] = make_float4(lv[0], lv[1], lv[2], lv[3]);
        }
        __syncthreads();

#pragma unroll
        for (int ks = 0; ks < 2; ++ks) {
            const int k0 = ks * 8 + q4;
            unsigned ah[2][4], al[2][4];
#pragma unroll
            for (int mt = 0; mt < 2; ++mt) {
                int m0 = warpM * 32 + mt * 16 + g;
                ah[mt][0] = __float_as_uint(Ash[k0][m0]);
                ah[mt][1] = __float_as_uint(Ash[k0][m0 + 8]);
                ah[mt][2] = __float_as_uint(Ash[k0 + 4][m0]);
                ah[mt][3] = __float_as_uint(Ash[k0 + 4][m0 + 8]);
                al[mt][0] = __float_as_uint(Asl[k0][m0]);
                al[mt][1] = __float_as_uint(Asl[k0][m0 + 8]);
                al[mt][2] = __float_as_uint(Asl[k0 + 4][m0]);
                al[mt][3] = __float_as_uint(Asl[k0 + 4][m0 + 8]);
            }
#pragma unroll
            for (int nt = 0; nt < 8; ++nt) {
                int n0 = warpN * 64 + nt * 8 + g;
                unsigned bh[2] = {__float_as_uint(Bsh[k0][n0]),
                                  __float_as_uint(Bsh[k0 + 4][n0])};
                unsigned bl[2] = {__float_as_uint(Bsl[k0][n0]),
                                  __float_as_uint(Bsl[k0 + 4][n0])};
#pragma unroll
                for (int mt = 0; mt < 2; ++mt) {
                    mma_tf32(acc[mt][nt], ah[mt], bh);
                    mma_tf32(acc[mt][nt], al[mt], bh);
                    mma_tf32(acc[mt][nt], ah[mt], bl);
                }
            }
        }
    }

    // epilogue
#pragma unroll
    for (int mt = 0; mt < 2; ++mt) {
        int row = rowBase + warpM * 32 + mt * 16 + g;
#pragma unroll
        for (int nt = 0; nt < 8; ++nt) {
            int col = colBase + warpN * 64 + nt * 8 + 2 * q4;
            *(float2*)&C[(size_t)row * N + col] =
                make_float2(acc[mt][nt][0], acc[mt][nt][1]);
            *(float2*)&C[(size_t)(row + 8) * N + col] =
                make_float2(acc[mt][nt][2], acc[mt][nt][3]);
        }
    }
}

// ============================================================
// RoPE in place on q [MROWS, NH*HD] and k [MROWS, KVH*HD].
// ============================================================
__global__ void rope_kernel(float* __restrict__ q, float* __restrict__ k)
{
    const int QP = MROWS * NH * (HD / 2);
    const int KP = MROWS * KVH * (HD / 2);
    int idx = blockIdx.x * blockDim.x + threadIdx.x;
    if (idx >= QP + KP) return;

    float* buf;
    int row, head, j, rowdim;
    if (idx < QP) {
        int t = idx;
        j = t & 31; t >>= 5;
        head = t & (NH - 1); t >>= 5;
        row = t;
        buf = q; rowdim = NH * HD;
    } else {
        int t = idx - QP;
        j = t & 31; t >>= 5;
        head = t & (KVH - 1); t >>= 3;
        row = t;
        buf = k; rowdim = KVH * HD;
    }
    int pos = row & (SEQ - 1);
    float inv_freq = exp2f(-(float)j * 0.41524101186092029f);
    float ang = (float)pos * inv_freq;
    float c, s;
    sincosf(ang, &s, &c);

    float* p = buf + (size_t)row * rowdim + head * HD + j;
    float x1 = p[0], x2 = p[32];
    p[0]  = x1 * c - x2 * s;
    p[32] = x2 * c + x1 * s;
}

// ============================================================
// Flash attention with tf32x2 MMA. Non-causal, GQA.
// Grid: (SEQ/128, NH, BATCH). 256 thr = 8 warps, warp owns 16 q rows.
// Dynamic smem: Qs[128][68] + Ps[128][68] + (Kth,Ktl,Vh,Vl)[64][68]
//             = 139264 bytes.
// ============================================================
__global__ void __launch_bounds__(256)
attn_kernel(const float* __restrict__ q, const float* __restrict__ k,
            const float* __restrict__ v, float* __restrict__ o)
{
    extern __shared__ float sm[];
    float* Qs  = sm;                     // [128][68] fp32 (scaled)
    float* Ps  = sm + 128 * 68;          // [128][68] fp32 probs
    float* Kth = sm + 2 * 128 * 68;      // [64 d][68 key] hi
    float* Ktl = Kth + 64 * 68;          // lo
    float* Vh  = Ktl + 64 * 68;          // [64 key][68 d] hi
    float* Vl  = Vh + 64 * 68;           // lo

    const int tid  = threadIdx.x;
    const int lane = tid & 31;
    const int wid  = tid >> 5;
    const int g    = lane >> 2;
    const int q4   = lane & 3;
    const int qb   = blockIdx.x * 128;
    const int h    = blockIdx.y;
    const int b    = blockIdx.z;
    const int kvh  = h >> 2;

    const float* qg = q + (size_t)b * SEQ * HID + (size_t)h * HD;
    const float* kg = k + (size_t)b * SEQ * KVDIM + (size_t)kvh * HD;
    const float* vg = v + (size_t)b * SEQ * KVDIM + (size_t)kvh * HD;
    float* og = o + (size_t)b * SEQ * HID + (size_t)h * HD;

    // load Q tile (128x64), fold in 1/sqrt(64)
#pragma unroll
    for (int p = 0; p < 8; ++p) {
        int id = tid + p * 256;
        int m = id >> 4, d4 = (id & 15) * 4;
        float4 vq = *(const float4*)&qg[(size_t)(qb + m) * HID + d4];
        vq.x *= 0.125f; vq.y *= 0.125f; vq.z *= 0.125f; vq.w *= 0.125f;
        *(float4*)&Qs[m * 68 + d4] = vq;
    }

    const int m0 = wid * 16 + g;   // warp-local row (lane-row A); row B = m0+8
    float Oa[8][4] = {};
    float miA = -3.0e38f, miB = -3.0e38f, liA = 0.0f, liB = 0.0f;

    for (int kb = 0; kb < SEQ; kb += 64) {
        __syncthreads();
        // load K (transpose+split) and V (split)
#pragma unroll
        for (int p = 0; p < 4; ++p) {
            int id = tid + p * 256;
            int n = id >> 4, d4 = (id & 15) * 4;
            float4 kv = *(const float4*)&kg[(size_t)(kb + n) * KVDIM + d4];
            float ka[4] = {kv.x, kv.y, kv.z, kv.w};
#pragma unroll
            for (int j = 0; j < 4; ++j) {
                unsigned hh, ll;
                split_tf32(ka[j], hh, ll);
                Kth[(d4 + j) * 68 + n] = __uint_as_float(hh);
                Ktl[(d4 + j) * 68 + n] = __uint_as_float(ll);
            }
            float4 vv = *(const float4*)&vg[(size_t)(kb + n) * KVDIM + d4];
            float va[4] = {vv.x, vv.y, vv.z, vv.w};
            float hv[4], lv[4];
#pragma unroll
            for (int j = 0; j < 4; ++j) {
                unsigned hh, ll;
                split_tf32(va[j], hh, ll);
                hv[j] = __uint_as_float(hh);
                lv[j] = __uint_as_float(ll);
            }
            *(float4*)&Vh[n * 68 + d4] = make_float4(hv[0], hv[1], hv[2], hv[3]);
            *(float4*)&Vl[n * 68 + d4] = make_float4(lv[0], lv[1], lv[2], lv[3]);
        }
        __syncthreads();

        // ---- S = Q @ K^T  (16 rows x 64 keys per warp) ----
        float S[8][4] = {};
#pragma unroll
        for (int kt = 0; kt < 8; ++kt) {
            int c0 = kt * 8 + q4;
            float qa[4] = {Qs[m0 * 68 + c0], Qs[(m0 + 8) * 68 + c0],
                           Qs[m0 * 68 + c0 + 4], Qs[(m0 + 8) * 68 + c0 + 4]};
            unsigned ah[4], al[4];
#pragma unroll
            for (int j = 0; j < 4; ++j) split_tf32(qa[j], ah[j], al[j]);
#pragma unroll
            for (int nt = 0; nt < 8; ++nt) {
                int n0 = nt * 8 + g;
                unsigned bh[2] = {__float_as_uint(Kth[c0 * 68 + n0]),
                                  __float_as_uint(Kth[(c0 + 4) * 68 + n0])};
                unsigned bl[2] = {__float_as_uint(Ktl[c0 * 68 + n0]),
                                  __float_as_uint(Ktl[(c0 + 4) * 68 + n0])};
                mma_tf32(S[nt], ah, bh);
                mma_tf32(S[nt], al, bh);
                mma_tf32(S[nt], ah, bl);
            }
        }

        // ---- online softmax (rows m0 and m0+8, per warp) ----
        float mA = -3.0e38f, mB = -3.0e38f;
#pragma unroll
        for (int nt = 0; nt < 8; ++nt) {
            mA = fmaxf(mA, fmaxf(S[nt][0], S[nt][1]));
            mB = fmaxf(mB, fmaxf(S[nt][2], S[nt][3]));
        }
        mA = fmaxf(mA, __shfl_xor_sync(0xffffffffu, mA, 1));
        mA = fmaxf(mA, __shfl_xor_sync(0xffffffffu, mA, 2));
        mB = fmaxf(mB, __shfl_xor_sync(0xffffffffu, mB, 1));
        mB = fmaxf(mB, __shfl_xor_sync(0xffffffffu, mB, 2));

        float mnA = fmaxf(miA, mA), mnB = fmaxf(miB, mB);
        float aA = __expf(miA - mnA), aB = __expf(miB - mnB);
        miA = mnA; miB = mnB;

        float sA = 0.0f, sB = 0.0f;
#pragma unroll
        for (int nt = 0; nt < 8; ++nt) {
            S[nt][0] = __expf(S[nt][0] - mnA);
            S[nt][1] = __expf(S[nt][1] - mnA);
            S[nt][2] = __expf(S[nt][2] - mnB);
            S[nt][3] = __expf(S[nt][3] - mnB);
            sA += S[nt][0] + S[nt][1];
            sB += S[nt][2] + S[nt][3];
        }
        sA += __shfl_xor_sync(0xffffffffu, sA, 1);
        sA += __shfl_xor_sync(0xffffffffu, sA, 2);
        sB += __shfl_xor_sync(0xffffffffu, sB, 1);
        sB += __shfl_xor_sync(0xffffffffu, sB, 2);
        liA = liA * aA + sA;
        liB = liB * aB + sB;

#pragma unroll
        for (int nt = 0; nt < 8; ++nt) {
            Oa[nt][0] *= aA; Oa[nt][1] *= aA;
            Oa[nt][2] *= aB; Oa[nt][3] *= aB;
            *(float2*)&Ps[m0 * 68 + nt * 8 + 2 * q4] = make_float2(S[nt][0], S[nt][1]);
            *(float2*)&Ps[(m0 + 8) * 68 + nt * 8 + 2 * q4] = make_float2(S[nt][2], S[nt][3]);
        }
        __syncwarp();

        // ---- O += P @ V ----
#pragma unroll
        for (int kt = 0; kt < 8; ++kt) {
            int c0 = kt * 8 + q4;
            float pa[4] = {Ps[m0 * 68 + c0], Ps[(m0 + 8) * 68 + c0],
                           Ps[m0 * 68 + c0 + 4], Ps[(m0 + 8) * 68 + c0 + 4]};
            unsigned ah[4], al[4];
#pragma unroll
            for (int j = 0; j < 4; ++j) split_tf32(pa[j], ah[j], al[j]);
#pragma unroll
            for (int nt = 0; nt < 8; ++nt) {
                int n0 = nt * 8 + g;
                unsigned bh[2] = {__float_as_uint(Vh[c0 * 68 + n0]),
                                  __float_as_uint(Vh[(c0 + 4) * 68 + n0])};
                unsigned bl[2] = {__float_as_uint(Vl[c0 * 68 + n0]),
                                  __float_as_uint(Vl[(c0 + 4) * 68 + n0])};
                mma_tf32(Oa[nt], ah, bh);
                mma_tf32(Oa[nt], al, bh);
                mma_tf32(Oa[nt], ah, bl);
            }
        }
    }

    // epilogue: normalize, store [b, s, h, d]
    float invA = 1.0f / liA, invB = 1.0f / liB;
#pragma unroll
    for (int nt = 0; nt < 8; ++nt) {
        int col = nt * 8 + 2 * q4;
        *(float2*)&og[(size_t)(qb + m0) * HID + col] =
            make_float2(Oa[nt][0] * invA, Oa[nt][1] * invA);
        *(float2*)&og[(size_t)(qb + m0 + 8) * HID + col] =
            make_float2(Oa[nt][2] * invB, Oa[nt][3] * invB);
    }
}

// ============================================================
// launch
// ============================================================
extern "C" void kernel_launch(void* const* d_in, const int* in_sizes, int n_in,
                              void* d_out, int out_size)
{
    const float* x  = (const float*)d_in[0];
    const float* wq = (const float*)d_in[1];
    const float* wk = (const float*)d_in[2];
    const float* wv = (const float*)d_in[3];
    const float* wo = (const float*)d_in[4];
    float* out = (float*)d_out;

    float *qp, *kp, *vp, *ap;
    cudaGetSymbolAddress((void**)&qp, g_q);
    cudaGetSymbolAddress((void**)&kp, g_k);
    cudaGetSymbolAddress((void**)&vp, g_v);
    cudaGetSymbolAddress((void**)&ap, g_att);

    dim3 blk(256);

    // QKV projections
    gemm_tf32_kernel<<<dim3(HID / 128, MROWS / 128), blk>>>(x, wq, qp, MROWS, HID, HID);
    gemm_tf32_kernel<<<dim3(KVDIM / 128, MROWS / 128), blk>>>(x, wk, kp, MROWS, KVDIM, HID);
    gemm_tf32_kernel<<<dim3(KVDIM / 128, MROWS / 128), blk>>>(x, wv, vp, MROWS, KVDIM, HID);

    // RoPE
    int total = MROWS * NH * (HD / 2) + MROWS * KVH * (HD / 2);
    rope_kernel<<<(total + 255) / 256, 256>>>(qp, kp);

    // attention
    cudaFuncSetAttribute(attn_kernel, cudaFuncAttributeMaxDynamicSharedMemorySize, 139264);
    attn_kernel<<<dim3(SEQ / 128, NH, BATCH), blk, 139264>>>(qp, kp, vp, ap);

    // output projection -> d_out
    gemm_tf32_kernel<<<dim3(HID / 128, MROWS / 128), blk>>>(ap, wo, out, MROWS, HID, HID);
}